// round 16
// baseline (speedup 1.0000x reference)
#include <cuda_runtime.h>
#include <cuda_fp16.h>
#include <stdint.h>
#include <math.h>

#define BATCH   2
#define SEQ     2048
#define DMODEL  1024
#define NHEADS  16
#define DK      64
#define NQ      (BATCH * SEQ)   // 4096 rows
#define GK      DMODEL

// fp16 scratch (allocation-free: device globals)
__device__ __half g_xh [NQ * DMODEL];
__device__ __half g_wq [DMODEL * DMODEL];
__device__ __half g_wk [DMODEL * DMODEL];
__device__ __half g_wv [DMODEL * DMODEL];
__device__ __half g_wo [DMODEL * DMODEL];
__device__ __half g_q  [BATCH * NHEADS * SEQ * DK];   // pre-scaled by 0.125*log2(e)
__device__ __half g_k  [BATCH * NHEADS * SEQ * DK];
__device__ __half g_v  [BATCH * NHEADS * SEQ * DK];
__device__ __half g_ctx[NQ * DMODEL];
__device__ float  g_cos[SEQ * 32];
__device__ float  g_sin[SEQ * 32];

// ---------------------------------------------------------------------------
// Fused setup kernel: blocks 0-255 build the RoPE table; the rest convert
// x + 4 weights to fp16.
// ---------------------------------------------------------------------------
#define NX2 (NQ * DMODEL / 2)          // 2097152
#define NW2 (DMODEL * DMODEL / 2)      // 524288
#define TBLOCKS 256                    // SEQ*32/256

__global__ __launch_bounds__(256) void setup_kernel(
    const float* __restrict__ x,  const float* __restrict__ wq,
    const float* __restrict__ wk, const float* __restrict__ wv,
    const float* __restrict__ wo)
{
    if (blockIdx.x < TBLOCKS) {
        int i = blockIdx.x * 256 + threadIdx.x;   // SEQ*32 = 65536
        int s = i >> 5;
        int j = i & 31;
        float freq = powf(10000.0f, -(float)(2 * j) * (1.0f / 64.0f));
        float sn, cs;
        sincosf((float)s * freq, &sn, &cs);
        g_cos[i] = cs;
        g_sin[i] = sn;
        return;
    }
    int i = (blockIdx.x - TBLOCKS) * 256 + threadIdx.x;
    const float2* s;
    __half2* d;
    int j;
    if (i < NX2)                { s = (const float2*)x;  d = (__half2*)g_xh; j = i; }
    else if (i < NX2 + NW2)     { s = (const float2*)wq; d = (__half2*)g_wq; j = i - NX2; }
    else if (i < NX2 + 2 * NW2) { s = (const float2*)wk; d = (__half2*)g_wk; j = i - NX2 - NW2; }
    else if (i < NX2 + 3 * NW2) { s = (const float2*)wv; d = (__half2*)g_wv; j = i - NX2 - 2 * NW2; }
    else                        { s = (const float2*)wo; d = (__half2*)g_wo; j = i - NX2 - 3 * NW2; }
    d[j] = __float22half2_rn(s[j]);
}

// ---------------------------------------------------------------------------
// Helpers
// ---------------------------------------------------------------------------
__device__ __forceinline__ unsigned f2h2(float x, float y)
{
    __half2 h = __float22half2_rn(make_float2(x, y));
    return *(unsigned*)&h;
}

__device__ __forceinline__ float ex2(float x)
{
    float y;
    asm("ex2.approx.ftz.f32 %0, %1;" : "=f"(y) : "f"(x));
    return y;
}

__device__ __forceinline__ void mma_f16(float* d, const unsigned* a, const unsigned* b)
{
    asm volatile(
        "mma.sync.aligned.m16n8k16.row.col.f32.f16.f16.f32 "
        "{%0,%1,%2,%3},{%4,%5,%6,%7},{%8,%9},{%0,%1,%2,%3};"
        : "+f"(d[0]), "+f"(d[1]), "+f"(d[2]), "+f"(d[3])
        : "r"(a[0]), "r"(a[1]), "r"(a[2]), "r"(a[3]), "r"(b[0]), "r"(b[1]));
}

__device__ __forceinline__ uint32_t smem_u32(const void* p)
{
    uint32_t a;
    asm("{ .reg .u64 t; cvta.to.shared.u64 t, %1; cvt.u32.u64 %0, t; }"
        : "=r"(a) : "l"(p));
    return a;
}

__device__ __forceinline__ void cp16(uint32_t saddr, const void* g)
{
    asm volatile("cp.async.cg.shared.global [%0], [%1], 16;"
                 :: "r"(saddr), "l"(g) : "memory");
}
#define CP_COMMIT() asm volatile("cp.async.commit_group;" ::: "memory")
#define CP_WAIT1()  asm volatile("cp.async.wait_group 1;" ::: "memory")

__device__ __forceinline__ void ldsm4(unsigned* r, uint32_t a)
{
    asm volatile("ldmatrix.sync.aligned.m8n8.x4.shared.b16 {%0,%1,%2,%3}, [%4];"
                 : "=r"(r[0]), "=r"(r[1]), "=r"(r[2]), "=r"(r[3]) : "r"(a));
}
__device__ __forceinline__ void ldsm4t(unsigned* r, uint32_t a)
{
    asm volatile("ldmatrix.sync.aligned.m8n8.x4.trans.shared.b16 {%0,%1,%2,%3}, [%4];"
                 : "=r"(r[0]), "=r"(r[1]), "=r"(r[2]), "=r"(r[3]) : "r"(a));
}

// ---------------------------------------------------------------------------
// fp16 cp.async GEMM, ldmatrix fragments, 3-stage pipeline,
// __launch_bounds__(256,3): target <=85 regs -> 3 CTAs/SM (24 warps).
// CTA 128x128, 8 warps (2m x 4n), warp tile 64x32, BK=32.
// ---------------------------------------------------------------------------
#define BK2   32
#define NSTG  (GK / BK2)        // 32
#define RPIT  20
#define TILEU (128 * RPIT)
#define GEMM_SMEM (3 * 2 * TILEU * 4)   // 61440 B

template <int OUTMODE>
__global__ __launch_bounds__(256, 3) void gemm_kernel(float* __restrict__ Dout)
{
    extern __shared__ unsigned Sg[];
    const uint32_t sb = smem_u32(Sg);

    const int z = blockIdx.z;
    const __half* Ah = OUTMODE ? g_ctx : g_xh;
    const __half* Wh = OUTMODE ? g_wo : (z == 0 ? g_wq : (z == 1 ? g_wk : g_wv));

    const int tid  = threadIdx.x;
    const int lane = tid & 31;
    const int warp = tid >> 5;
    const int wm   = warp & 1;
    const int wn   = warp >> 1;
    const int m0   = blockIdx.y * 128;
    const int n0   = blockIdx.x * 128;
    const int g    = lane >> 2;
    const int t    = lane & 3;
    const int mat  = lane >> 3;
    const int mj   = lane & 7;

    const int row = tid >> 1;
    const int c0  = (tid & 1) * 2;
    const __half* ga = Ah + (size_t)(m0 + row) * GK + c0 * 8;
    const __half* gw = Wh + (size_t)(n0 + row) * GK + c0 * 8;
    const uint32_t da = sb + (row * RPIT + c0 * 4) * 4;

    auto issue = [&](int s, int p) {
        const uint32_t d0 = da + p * 2 * TILEU * 4;
        const __half* a = ga + s * BK2;
        const __half* w = gw + s * BK2;
        cp16(d0, a);
        cp16(d0 + 16, a + 8);
        cp16(d0 + TILEU * 4, w);
        cp16(d0 + TILEU * 4 + 16, w + 8);
    };

    float c[4][4][4];
    #pragma unroll
    for (int i = 0; i < 4; i++)
        #pragma unroll
        for (int j = 0; j < 4; j++)
            #pragma unroll
            for (int r = 0; r < 4; r++)
                c[i][j][r] = 0.f;

    issue(0, 0); CP_COMMIT();
    issue(1, 1); CP_COMMIT();

    for (int s = 0; s < NSTG; s++) {
        const int p = s % 3;
        CP_WAIT1();
        __syncthreads();
        if (s + 2 < NSTG) { issue(s + 2, (s + 2) % 3); CP_COMMIT(); }

        const unsigned base = p * 2 * TILEU;
        #pragma unroll
        for (int kc = 0; kc < 2; kc++) {
            unsigned af[4][4], bf[4][2];
            #pragma unroll
            for (int mf = 0; mf < 4; mf++) {
                const uint32_t a = sb + (base +
                    (wm * 64 + mf * 16 + (mat & 1) * 8 + mj) * RPIT +
                    kc * 8 + (mat >> 1) * 4) * 4;
                ldsm4(af[mf], a);
            }
            #pragma unroll
            for (int ntp = 0; ntp < 2; ntp++) {
                unsigned r[4];
                const uint32_t a = sb + (base + TILEU +
                    (wn * 32 + ntp * 16 + (mat >> 1) * 8 + mj) * RPIT +
                    kc * 8 + (mat & 1) * 4) * 4;
                ldsm4(r, a);
                bf[2 * ntp][0]     = r[0]; bf[2 * ntp][1]     = r[1];
                bf[2 * ntp + 1][0] = r[2]; bf[2 * ntp + 1][1] = r[3];
            }
            #pragma unroll
            for (int mf = 0; mf < 4; mf++)
                #pragma unroll
                for (int nf = 0; nf < 4; nf++)
                    mma_f16(c[mf][nf], af[mf], bf[nf]);
        }
    }
    __syncthreads();

    __half* dsth = (OUTMODE == 0) ? (z == 0 ? g_q : (z == 1 ? g_k : g_v)) : 0;
    #pragma unroll
    for (int mf = 0; mf < 4; mf++) {
        #pragma unroll
        for (int nf = 0; nf < 4; nf++) {
            const int col = n0 + wn * 32 + nf * 8 + t * 2;
            #pragma unroll
            for (int half = 0; half < 2; half++) {
                const int r  = m0 + wm * 64 + mf * 16 + g + half * 8;
                float x0 = c[mf][nf][half * 2 + 0];
                float x1 = c[mf][nf][half * 2 + 1];
                if (OUTMODE) {
                    *(float2*)&Dout[(size_t)r * DMODEL + col] = make_float2(x0, x1);
                } else {
                    const int bb = r >> 11;
                    const int sI = r & (SEQ - 1);
                    const int h  = col >> 6;
                    const int dd = col & 63;
                    const int base = ((bb * NHEADS + h) * SEQ + sI) * DK + dd;
                    if (z < 2) {
                        const float cs = g_cos[sI * 32 + (dd >> 1)];
                        const float sn = g_sin[sI * 32 + (dd >> 1)];
                        float r0 = x0 * cs - x1 * sn;
                        float r1 = x0 * sn + x1 * cs;
                        if (z == 0) {
                            // fold 1/sqrt(dk) AND log2(e) for exp2-softmax
                            const float qs = 0.125f * 1.4426950408889634f;
                            r0 *= qs; r1 *= qs;
                        }
                        *(unsigned*)&dsth[base] = f2h2(r0, r1);
                    } else {
                        *(unsigned*)&dsth[base] = f2h2(x0, x1);
                    }
                }
            }
        }
    }
}

// ---------------------------------------------------------------------------
// fp16 flash attention — R14 version (87.8 us, frozen).
// ---------------------------------------------------------------------------
#define APIT  36
#define KVBUF (64 * APIT)   // 2304 uints
#define ATTN_SMEM_BYTES ((6 * KVBUF + 4 * 16 * APIT) * 4)   // 64512

__global__ __launch_bounds__(128) void attn_mma_kernel()
{
    extern __shared__ unsigned sm[];
    const uint32_t sb = smem_u32(sm);
    unsigned* Pw = sm + 6 * KVBUF + (threadIdx.x >> 5) * 16 * APIT;

    const int tid  = threadIdx.x;
    const int lane = tid & 31;
    const int warp = tid >> 5;
    const int gid  = lane >> 2;
    const int tig  = lane & 3;
    const int mat  = lane >> 3;
    const int mj   = lane & 7;

    const int h  = blockIdx.y;
    const int b  = blockIdx.z;
    const int qb = gridDim.x - 1 - blockIdx.x;   // heavy blocks first
    const int q0 = qb * 64;

    const __half* kbase = g_k + (size_t)((b * NHEADS + h) * SEQ) * DK;
    const __half* vbase = g_v + (size_t)((b * NHEADS + h) * SEQ) * DK;

    auto stage = [&](int kt, int buf) {
        #pragma unroll
        for (int i = 0; i < 4; i++) {
            const int idx = i * 128 + tid;
            const int key = idx >> 3;
            const int c8  = idx & 7;
            const uint32_t doff = (key * APIT + c8 * 4) * 4;
            cp16(sb + buf * KVBUF * 4 + doff,
                 kbase + (size_t)(kt * 64 + key) * 64 + c8 * 8);
            cp16(sb + (3 + buf) * KVBUF * 4 + doff,
                 vbase + (size_t)(kt * 64 + key) * 64 + c8 * 8);
        }
    };

    // Q fragments (pre-scaled by 0.125*log2e at projection)
    unsigned qf[4][4];
    {
        const unsigned* qp =
            (const unsigned*)(g_q + (size_t)((b * NHEADS + h) * SEQ + q0) * DK);
        const int r0 = warp * 16 + gid;
        #pragma unroll
        for (int kc = 0; kc < 4; kc++) {
            qf[kc][0] = qp[r0 * 32 + kc * 8 + tig];
            qf[kc][1] = qp[(r0 + 8) * 32 + kc * 8 + tig];
            qf[kc][2] = qp[r0 * 32 + kc * 8 + tig + 4];
            qf[kc][3] = qp[(r0 + 8) * 32 + kc * 8 + tig + 4];
        }
    }

    float o[8][4];
    #pragma unroll
    for (int nt = 0; nt < 8; nt++)
        #pragma unroll
        for (int r = 0; r < 4; r++)
            o[nt][r] = 0.f;
    float m0v = -1e30f, m1v = -1e30f, l0 = 0.f, l1 = 0.f;

    const int ntiles = qb + 1;
    stage(0, 0);
    CP_COMMIT();
    if (ntiles > 1) stage(1, 1);
    CP_COMMIT();

    for (int kt = 0; kt < ntiles; kt++) {
        const int cur = kt % 3;
        CP_WAIT1();
        __syncthreads();
        if (kt + 2 < ntiles) stage(kt + 2, (kt + 2) % 3);
        CP_COMMIT();

        // S = Q K^T (log2 domain)
        float s[8][4];
        #pragma unroll
        for (int nt = 0; nt < 8; nt++)
            s[nt][0] = s[nt][1] = s[nt][2] = s[nt][3] = 0.f;
        #pragma unroll
        for (int kc = 0; kc < 4; kc++) {
            #pragma unroll
            for (int ntp = 0; ntp < 4; ntp++) {
                const uint32_t a = sb +
                    (cur * KVBUF + (ntp * 16 + (mat >> 1) * 8 + mj) * APIT +
                     kc * 8 + (mat & 1) * 4) * 4;
                unsigned r[4];
                ldsm4(r, a);
                mma_f16(s[2 * ntp],     qf[kc], r);
                mma_f16(s[2 * ntp + 1], qf[kc], r + 2);
            }
        }

        if (kt == qb) {
            const int r0 = warp * 16 + gid;
            #pragma unroll
            for (int nt = 0; nt < 8; nt++) {
                const int c = nt * 8 + 2 * tig;
                if (c > r0)         s[nt][0] = -1e30f;
                if (c + 1 > r0)     s[nt][1] = -1e30f;
                if (c > r0 + 8)     s[nt][2] = -1e30f;
                if (c + 1 > r0 + 8) s[nt][3] = -1e30f;
            }
        }

        float mx0 = -1e30f, mx1 = -1e30f;
        #pragma unroll
        for (int nt = 0; nt < 8; nt++) {
            mx0 = fmaxf(mx0, fmaxf(s[nt][0], s[nt][1]));
            mx1 = fmaxf(mx1, fmaxf(s[nt][2], s[nt][3]));
        }
        mx0 = fmaxf(mx0, __shfl_xor_sync(0xffffffffu, mx0, 1));
        mx0 = fmaxf(mx0, __shfl_xor_sync(0xffffffffu, mx0, 2));
        mx1 = fmaxf(mx1, __shfl_xor_sync(0xffffffffu, mx1, 1));
        mx1 = fmaxf(mx1, __shfl_xor_sync(0xffffffffu, mx1, 2));

        const float nm0 = fmaxf(m0v, mx0);
        const float nm1 = fmaxf(m1v, mx1);
        const float al0 = ex2(m0v - nm0);
        const float al1 = ex2(m1v - nm1);
        m0v = nm0; m1v = nm1;

        float rs0 = 0.f, rs1 = 0.f;
        #pragma unroll
        for (int nt = 0; nt < 8; nt++) {
            const float p0 = ex2(s[nt][0] - m0v);
            const float p1 = ex2(s[nt][1] - m0v);
            const float p2 = ex2(s[nt][2] - m1v);
            const float p3 = ex2(s[nt][3] - m1v);
            rs0 += p0 + p1;
            rs1 += p2 + p3;
            Pw[gid * APIT + nt * 4 + tig]       = f2h2(p0, p1);
            Pw[(gid + 8) * APIT + nt * 4 + tig] = f2h2(p2, p3);
        }
        rs0 += __shfl_xor_sync(0xffffffffu, rs0, 1);
        rs0 += __shfl_xor_sync(0xffffffffu, rs0, 2);
        rs1 += __shfl_xor_sync(0xffffffffu, rs1, 1);
        rs1 += __shfl_xor_sync(0xffffffffu, rs1, 2);
        l0 = l0 * al0 + rs0;
        l1 = l1 * al1 + rs1;

        #pragma unroll
        for (int nt = 0; nt < 8; nt++) {
            o[nt][0] *= al0; o[nt][1] *= al0;
            o[nt][2] *= al1; o[nt][3] *= al1;
        }

        __syncwarp();

        // O += P @ V
        #pragma unroll
        for (int kcv = 0; kcv < 4; kcv++) {
            unsigned af[4];
            af[0] = Pw[gid * APIT + kcv * 8 + tig];
            af[1] = Pw[(gid + 8) * APIT + kcv * 8 + tig];
            af[2] = Pw[gid * APIT + kcv * 8 + tig + 4];
            af[3] = Pw[(gid + 8) * APIT + kcv * 8 + tig + 4];
            #pragma unroll
            for (int ntp = 0; ntp < 4; ntp++) {
                const uint32_t a = sb +
                    ((3 + cur) * KVBUF + (kcv * 16 + (mat & 1) * 8 + mj) * APIT +
                     ntp * 8 + (mat >> 1) * 4) * 4;
                unsigned r[4];
                ldsm4t(r, a);
                mma_f16(o[2 * ntp],     af, r);
                mma_f16(o[2 * ntp + 1], af, r + 2);
            }
        }
    }

    // Epilogue
    const float il0 = 1.0f / l0;
    const float il1 = 1.0f / l1;
    __half* ob = g_ctx + (size_t)(b * SEQ + q0 + warp * 16) * DMODEL + h * 64;
    #pragma unroll
    for (int nt = 0; nt < 8; nt++) {
        const int col = nt * 8 + 2 * tig;
        *(unsigned*)&ob[gid * DMODEL + col] =
            f2h2(o[nt][0] * il0, o[nt][1] * il0);
        *(unsigned*)&ob[(gid + 8) * DMODEL + col] =
            f2h2(o[nt][2] * il1, o[nt][3] * il1);
    }
}

// ---------------------------------------------------------------------------
extern "C" void kernel_launch(void* const* d_in, const int* in_sizes, int n_in,
                              void* d_out, int out_size)
{
    const float* x  = (const float*)d_in[0];
    const float* Wq = (const float*)d_in[1];
    const float* Wk = (const float*)d_in[2];
    const float* Wv = (const float*)d_in[3];
    const float* Wo = (const float*)d_in[4];
    float* out = (float*)d_out;

    cudaFuncSetAttribute(gemm_kernel<0>,
                         cudaFuncAttributeMaxDynamicSharedMemorySize, GEMM_SMEM);
    cudaFuncSetAttribute(gemm_kernel<1>,
                         cudaFuncAttributeMaxDynamicSharedMemorySize, GEMM_SMEM);
    cudaFuncSetAttribute(attn_mma_kernel,
                         cudaFuncAttributeMaxDynamicSharedMemorySize,
                         ATTN_SMEM_BYTES);

    setup_kernel<<<TBLOCKS + (NX2 + 4 * NW2) / 256, 256>>>(x, Wq, Wk, Wv, Wo);

    dim3 gq(DMODEL / 128, NQ / 128, 3);
    gemm_kernel<0><<<gq, 256, GEMM_SMEM>>>(0);

    dim3 ga(SEQ / 64, NHEADS, BATCH);
    attn_mma_kernel<<<ga, 128, ATTN_SMEM_BYTES>>>();

    dim3 go(DMODEL / 128, NQ / 128, 1);
    gemm_kernel<1><<<go, 256, GEMM_SMEM>>>(out);
}

// round 17
// speedup vs baseline: 1.1994x; 1.1994x over previous
#include <cuda_runtime.h>
#include <cuda_fp16.h>
#include <stdint.h>
#include <math.h>

#define BATCH   2
#define SEQ     2048
#define DMODEL  1024
#define NHEADS  16
#define DK      64
#define NQ      (BATCH * SEQ)   // 4096 rows
#define GK      DMODEL

// fp16 scratch (allocation-free: device globals)
__device__ __half g_xh [NQ * DMODEL];
__device__ __half g_wq [DMODEL * DMODEL];
__device__ __half g_wk [DMODEL * DMODEL];
__device__ __half g_wv [DMODEL * DMODEL];
__device__ __half g_wo [DMODEL * DMODEL];
__device__ __half g_q  [BATCH * NHEADS * SEQ * DK];   // pre-scaled by 0.125*log2(e)
__device__ __half g_k  [BATCH * NHEADS * SEQ * DK];
__device__ __half g_v  [BATCH * NHEADS * SEQ * DK];
__device__ __half g_ctx[NQ * DMODEL];
__device__ float  g_cos[SEQ * 32];
__device__ float  g_sin[SEQ * 32];

// ---------------------------------------------------------------------------
// Fused setup kernel: blocks 0-255 build the RoPE table; the rest convert
// x + 4 weights to fp16. One launch instead of two.
// ---------------------------------------------------------------------------
#define NX2 (NQ * DMODEL / 2)          // 2097152
#define NW2 (DMODEL * DMODEL / 2)      // 524288
#define TBLOCKS 256                    // SEQ*32/256

__global__ __launch_bounds__(256) void setup_kernel(
    const float* __restrict__ x,  const float* __restrict__ wq,
    const float* __restrict__ wk, const float* __restrict__ wv,
    const float* __restrict__ wo)
{
    if (blockIdx.x < TBLOCKS) {
        int i = blockIdx.x * 256 + threadIdx.x;   // SEQ*32 = 65536
        int s = i >> 5;
        int j = i & 31;
        float freq = powf(10000.0f, -(float)(2 * j) * (1.0f / 64.0f));
        float sn, cs;
        sincosf((float)s * freq, &sn, &cs);
        g_cos[i] = cs;
        g_sin[i] = sn;
        return;
    }
    int i = (blockIdx.x - TBLOCKS) * 256 + threadIdx.x;
    const float2* s;
    __half2* d;
    int j;
    if (i < NX2)                { s = (const float2*)x;  d = (__half2*)g_xh; j = i; }
    else if (i < NX2 + NW2)     { s = (const float2*)wq; d = (__half2*)g_wq; j = i - NX2; }
    else if (i < NX2 + 2 * NW2) { s = (const float2*)wk; d = (__half2*)g_wk; j = i - NX2 - NW2; }
    else if (i < NX2 + 3 * NW2) { s = (const float2*)wv; d = (__half2*)g_wv; j = i - NX2 - 2 * NW2; }
    else                        { s = (const float2*)wo; d = (__half2*)g_wo; j = i - NX2 - 3 * NW2; }
    d[j] = __float22half2_rn(s[j]);
}

// ---------------------------------------------------------------------------
// Helpers
// ---------------------------------------------------------------------------
__device__ __forceinline__ unsigned f2h2(float x, float y)
{
    __half2 h = __float22half2_rn(make_float2(x, y));
    return *(unsigned*)&h;
}

__device__ __forceinline__ float ex2(float x)
{
    float y;
    asm("ex2.approx.ftz.f32 %0, %1;" : "=f"(y) : "f"(x));
    return y;
}

__device__ __forceinline__ void mma_f16(float* d, const unsigned* a, const unsigned* b)
{
    asm volatile(
        "mma.sync.aligned.m16n8k16.row.col.f32.f16.f16.f32 "
        "{%0,%1,%2,%3},{%4,%5,%6,%7},{%8,%9},{%0,%1,%2,%3};"
        : "+f"(d[0]), "+f"(d[1]), "+f"(d[2]), "+f"(d[3])
        : "r"(a[0]), "r"(a[1]), "r"(a[2]), "r"(a[3]), "r"(b[0]), "r"(b[1]));
}

__device__ __forceinline__ uint32_t smem_u32(const void* p)
{
    uint32_t a;
    asm("{ .reg .u64 t; cvta.to.shared.u64 t, %1; cvt.u32.u64 %0, t; }"
        : "=r"(a) : "l"(p));
    return a;
}

__device__ __forceinline__ void cp16(uint32_t saddr, const void* g)
{
    asm volatile("cp.async.cg.shared.global [%0], [%1], 16;"
                 :: "r"(saddr), "l"(g) : "memory");
}
#define CP_COMMIT() asm volatile("cp.async.commit_group;" ::: "memory")
#define CP_WAIT1()  asm volatile("cp.async.wait_group 1;" ::: "memory")

__device__ __forceinline__ void ldsm4(unsigned* r, uint32_t a)
{
    asm volatile("ldmatrix.sync.aligned.m8n8.x4.shared.b16 {%0,%1,%2,%3}, [%4];"
                 : "=r"(r[0]), "=r"(r[1]), "=r"(r[2]), "=r"(r[3]) : "r"(a));
}
__device__ __forceinline__ void ldsm4t(unsigned* r, uint32_t a)
{
    asm volatile("ldmatrix.sync.aligned.m8n8.x4.trans.shared.b16 {%0,%1,%2,%3}, [%4];"
                 : "=r"(r[0]), "=r"(r[1]), "=r"(r[2]), "=r"(r[3]) : "r"(a));
}

// ---------------------------------------------------------------------------
// fp16 cp.async GEMM, ldmatrix fragments, 3-stage pipeline, NO reg cap
// (R12/R14 proven config). CTA 128x128, 8 warps, warp tile 64x32, BK=32.
// ---------------------------------------------------------------------------
#define BK2   32
#define NSTG  (GK / BK2)        // 32
#define RPIT  20
#define TILEU (128 * RPIT)
#define GEMM_SMEM (3 * 2 * TILEU * 4)   // 61440 B

template <int OUTMODE>
__global__ __launch_bounds__(256) void gemm_kernel(float* __restrict__ Dout)
{
    extern __shared__ unsigned Sg[];
    const uint32_t sb = smem_u32(Sg);

    const int z = blockIdx.z;
    const __half* Ah = OUTMODE ? g_ctx : g_xh;
    const __half* Wh = OUTMODE ? g_wo : (z == 0 ? g_wq : (z == 1 ? g_wk : g_wv));

    const int tid  = threadIdx.x;
    const int lane = tid & 31;
    const int warp = tid >> 5;
    const int wm   = warp & 1;
    const int wn   = warp >> 1;
    const int m0   = blockIdx.y * 128;
    const int n0   = blockIdx.x * 128;
    const int g    = lane >> 2;
    const int t    = lane & 3;
    const int mat  = lane >> 3;
    const int mj   = lane & 7;

    const int row = tid >> 1;
    const int c0  = (tid & 1) * 2;
    const __half* ga = Ah + (size_t)(m0 + row) * GK + c0 * 8;
    const __half* gw = Wh + (size_t)(n0 + row) * GK + c0 * 8;
    const uint32_t da = sb + (row * RPIT + c0 * 4) * 4;

    auto issue = [&](int s, int p) {
        const uint32_t d0 = da + p * 2 * TILEU * 4;
        const __half* a = ga + s * BK2;
        const __half* w = gw + s * BK2;
        cp16(d0, a);
        cp16(d0 + 16, a + 8);
        cp16(d0 + TILEU * 4, w);
        cp16(d0 + TILEU * 4 + 16, w + 8);
    };

    float c[4][4][4];
    #pragma unroll
    for (int i = 0; i < 4; i++)
        #pragma unroll
        for (int j = 0; j < 4; j++)
            #pragma unroll
            for (int r = 0; r < 4; r++)
                c[i][j][r] = 0.f;

    issue(0, 0); CP_COMMIT();
    issue(1, 1); CP_COMMIT();

    for (int s = 0; s < NSTG; s++) {
        const int p = s % 3;
        CP_WAIT1();
        __syncthreads();
        if (s + 2 < NSTG) { issue(s + 2, (s + 2) % 3); CP_COMMIT(); }

        const unsigned base = p * 2 * TILEU;
        #pragma unroll
        for (int kc = 0; kc < 2; kc++) {
            unsigned af[4][4], bf[4][2];
            #pragma unroll
            for (int mf = 0; mf < 4; mf++) {
                const uint32_t a = sb + (base +
                    (wm * 64 + mf * 16 + (mat & 1) * 8 + mj) * RPIT +
                    kc * 8 + (mat >> 1) * 4) * 4;
                ldsm4(af[mf], a);
            }
            #pragma unroll
            for (int ntp = 0; ntp < 2; ntp++) {
                unsigned r[4];
                const uint32_t a = sb + (base + TILEU +
                    (wn * 32 + ntp * 16 + (mat >> 1) * 8 + mj) * RPIT +
                    kc * 8 + (mat & 1) * 4) * 4;
                ldsm4(r, a);
                bf[2 * ntp][0]     = r[0]; bf[2 * ntp][1]     = r[1];
                bf[2 * ntp + 1][0] = r[2]; bf[2 * ntp + 1][1] = r[3];
            }
            #pragma unroll
            for (int mf = 0; mf < 4; mf++)
                #pragma unroll
                for (int nf = 0; nf < 4; nf++)
                    mma_f16(c[mf][nf], af[mf], bf[nf]);
        }
    }
    __syncthreads();

    __half* dsth = (OUTMODE == 0) ? (z == 0 ? g_q : (z == 1 ? g_k : g_v)) : 0;
    #pragma unroll
    for (int mf = 0; mf < 4; mf++) {
        #pragma unroll
        for (int nf = 0; nf < 4; nf++) {
            const int col = n0 + wn * 32 + nf * 8 + t * 2;
            #pragma unroll
            for (int half = 0; half < 2; half++) {
                const int r  = m0 + wm * 64 + mf * 16 + g + half * 8;
                float x0 = c[mf][nf][half * 2 + 0];
                float x1 = c[mf][nf][half * 2 + 1];
                if (OUTMODE) {
                    *(float2*)&Dout[(size_t)r * DMODEL + col] = make_float2(x0, x1);
                } else {
                    const int bb = r >> 11;
                    const int sI = r & (SEQ - 1);
                    const int h  = col >> 6;
                    const int dd = col & 63;
                    const int base = ((bb * NHEADS + h) * SEQ + sI) * DK + dd;
                    if (z < 2) {
                        const float cs = g_cos[sI * 32 + (dd >> 1)];
                        const float sn = g_sin[sI * 32 + (dd >> 1)];
                        float r0 = x0 * cs - x1 * sn;
                        float r1 = x0 * sn + x1 * cs;
                        if (z == 0) {
                            // fold 1/sqrt(dk) AND log2(e) for exp2-softmax
                            const float qs = 0.125f * 1.4426950408889634f;
                            r0 *= qs; r1 *= qs;
                        }
                        *(unsigned*)&dsth[base] = f2h2(r0, r1);
                    } else {
                        *(unsigned*)&dsth[base] = f2h2(x0, x1);
                    }
                }
            }
        }
    }
}

// ---------------------------------------------------------------------------
// fp16 flash attention — R14 version (87.8 us, frozen): 3-buffer cp.async,
// one barrier per tile, ldmatrix K/V frags, exp2-domain softmax.
// ---------------------------------------------------------------------------
#define APIT  36
#define KVBUF (64 * APIT)   // 2304 uints
#define ATTN_SMEM_BYTES ((6 * KVBUF + 4 * 16 * APIT) * 4)   // 64512

__global__ __launch_bounds__(128) void attn_mma_kernel()
{
    extern __shared__ unsigned sm[];
    const uint32_t sb = smem_u32(sm);
    unsigned* Pw = sm + 6 * KVBUF + (threadIdx.x >> 5) * 16 * APIT;

    const int tid  = threadIdx.x;
    const int lane = tid & 31;
    const int warp = tid >> 5;
    const int gid  = lane >> 2;
    const int tig  = lane & 3;
    const int mat  = lane >> 3;
    const int mj   = lane & 7;

    const int h  = blockIdx.y;
    const int b  = blockIdx.z;
    const int qb = gridDim.x - 1 - blockIdx.x;   // heavy blocks first
    const int q0 = qb * 64;

    const __half* kbase = g_k + (size_t)((b * NHEADS + h) * SEQ) * DK;
    const __half* vbase = g_v + (size_t)((b * NHEADS + h) * SEQ) * DK;

    auto stage = [&](int kt, int buf) {
        #pragma unroll
        for (int i = 0; i < 4; i++) {
            const int idx = i * 128 + tid;
            const int key = idx >> 3;
            const int c8  = idx & 7;
            const uint32_t doff = (key * APIT + c8 * 4) * 4;
            cp16(sb + buf * KVBUF * 4 + doff,
                 kbase + (size_t)(kt * 64 + key) * 64 + c8 * 8);
            cp16(sb + (3 + buf) * KVBUF * 4 + doff,
                 vbase + (size_t)(kt * 64 + key) * 64 + c8 * 8);
        }
    };

    // Q fragments (pre-scaled by 0.125*log2e at projection)
    unsigned qf[4][4];
    {
        const unsigned* qp =
            (const unsigned*)(g_q + (size_t)((b * NHEADS + h) * SEQ + q0) * DK);
        const int r0 = warp * 16 + gid;
        #pragma unroll
        for (int kc = 0; kc < 4; kc++) {
            qf[kc][0] = qp[r0 * 32 + kc * 8 + tig];
            qf[kc][1] = qp[(r0 + 8) * 32 + kc * 8 + tig];
            qf[kc][2] = qp[r0 * 32 + kc * 8 + tig + 4];
            qf[kc][3] = qp[(r0 + 8) * 32 + kc * 8 + tig + 4];
        }
    }

    float o[8][4];
    #pragma unroll
    for (int nt = 0; nt < 8; nt++)
        #pragma unroll
        for (int r = 0; r < 4; r++)
            o[nt][r] = 0.f;
    float m0v = -1e30f, m1v = -1e30f, l0 = 0.f, l1 = 0.f;

    const int ntiles = qb + 1;
    stage(0, 0);
    CP_COMMIT();
    if (ntiles > 1) stage(1, 1);
    CP_COMMIT();

    for (int kt = 0; kt < ntiles; kt++) {
        const int cur = kt % 3;
        CP_WAIT1();
        __syncthreads();
        if (kt + 2 < ntiles) stage(kt + 2, (kt + 2) % 3);
        CP_COMMIT();

        // S = Q K^T (log2 domain)
        float s[8][4];
        #pragma unroll
        for (int nt = 0; nt < 8; nt++)
            s[nt][0] = s[nt][1] = s[nt][2] = s[nt][3] = 0.f;
        #pragma unroll
        for (int kc = 0; kc < 4; kc++) {
            #pragma unroll
            for (int ntp = 0; ntp < 4; ntp++) {
                const uint32_t a = sb +
                    (cur * KVBUF + (ntp * 16 + (mat >> 1) * 8 + mj) * APIT +
                     kc * 8 + (mat & 1) * 4) * 4;
                unsigned r[4];
                ldsm4(r, a);
                mma_f16(s[2 * ntp],     qf[kc], r);
                mma_f16(s[2 * ntp + 1], qf[kc], r + 2);
            }
        }

        if (kt == qb) {
            const int r0 = warp * 16 + gid;
            #pragma unroll
            for (int nt = 0; nt < 8; nt++) {
                const int c = nt * 8 + 2 * tig;
                if (c > r0)         s[nt][0] = -1e30f;
                if (c + 1 > r0)     s[nt][1] = -1e30f;
                if (c > r0 + 8)     s[nt][2] = -1e30f;
                if (c + 1 > r0 + 8) s[nt][3] = -1e30f;
            }
        }

        float mx0 = -1e30f, mx1 = -1e30f;
        #pragma unroll
        for (int nt = 0; nt < 8; nt++) {
            mx0 = fmaxf(mx0, fmaxf(s[nt][0], s[nt][1]));
            mx1 = fmaxf(mx1, fmaxf(s[nt][2], s[nt][3]));
        }
        mx0 = fmaxf(mx0, __shfl_xor_sync(0xffffffffu, mx0, 1));
        mx0 = fmaxf(mx0, __shfl_xor_sync(0xffffffffu, mx0, 2));
        mx1 = fmaxf(mx1, __shfl_xor_sync(0xffffffffu, mx1, 1));
        mx1 = fmaxf(mx1, __shfl_xor_sync(0xffffffffu, mx1, 2));

        const float nm0 = fmaxf(m0v, mx0);
        const float nm1 = fmaxf(m1v, mx1);
        const float al0 = ex2(m0v - nm0);
        const float al1 = ex2(m1v - nm1);
        m0v = nm0; m1v = nm1;

        float rs0 = 0.f, rs1 = 0.f;
        #pragma unroll
        for (int nt = 0; nt < 8; nt++) {
            const float p0 = ex2(s[nt][0] - m0v);
            const float p1 = ex2(s[nt][1] - m0v);
            const float p2 = ex2(s[nt][2] - m1v);
            const float p3 = ex2(s[nt][3] - m1v);
            rs0 += p0 + p1;
            rs1 += p2 + p3;
            Pw[gid * APIT + nt * 4 + tig]       = f2h2(p0, p1);
            Pw[(gid + 8) * APIT + nt * 4 + tig] = f2h2(p2, p3);
        }
        rs0 += __shfl_xor_sync(0xffffffffu, rs0, 1);
        rs0 += __shfl_xor_sync(0xffffffffu, rs0, 2);
        rs1 += __shfl_xor_sync(0xffffffffu, rs1, 1);
        rs1 += __shfl_xor_sync(0xffffffffu, rs1, 2);
        l0 = l0 * al0 + rs0;
        l1 = l1 * al1 + rs1;

        #pragma unroll
        for (int nt = 0; nt < 8; nt++) {
            o[nt][0] *= al0; o[nt][1] *= al0;
            o[nt][2] *= al1; o[nt][3] *= al1;
        }

        __syncwarp();

        // O += P @ V
        #pragma unroll
        for (int kcv = 0; kcv < 4; kcv++) {
            unsigned af[4];
            af[0] = Pw[gid * APIT + kcv * 8 + tig];
            af[1] = Pw[(gid + 8) * APIT + kcv * 8 + tig];
            af[2] = Pw[gid * APIT + kcv * 8 + tig + 4];
            af[3] = Pw[(gid + 8) * APIT + kcv * 8 + tig + 4];
            #pragma unroll
            for (int ntp = 0; ntp < 4; ntp++) {
                const uint32_t a = sb +
                    ((3 + cur) * KVBUF + (kcv * 16 + (mat & 1) * 8 + mj) * APIT +
                     ntp * 8 + (mat >> 1) * 4) * 4;
                unsigned r[4];
                ldsm4t(r, a);
                mma_f16(o[2 * ntp],     af, r);
                mma_f16(o[2 * ntp + 1], af, r + 2);
            }
        }
    }

    // Epilogue
    const float il0 = 1.0f / l0;
    const float il1 = 1.0f / l1;
    __half* ob = g_ctx + (size_t)(b * SEQ + q0 + warp * 16) * DMODEL + h * 64;
    #pragma unroll
    for (int nt = 0; nt < 8; nt++) {
        const int col = nt * 8 + 2 * tig;
        *(unsigned*)&ob[gid * DMODEL + col] =
            f2h2(o[nt][0] * il0, o[nt][1] * il0);
        *(unsigned*)&ob[(gid + 8) * DMODEL + col] =
            f2h2(o[nt][2] * il1, o[nt][3] * il1);
    }
}

// ---------------------------------------------------------------------------
extern "C" void kernel_launch(void* const* d_in, const int* in_sizes, int n_in,
                              void* d_out, int out_size)
{
    const float* x  = (const float*)d_in[0];
    const float* Wq = (const float*)d_in[1];
    const float* Wk = (const float*)d_in[2];
    const float* Wv = (const float*)d_in[3];
    const float* Wo = (const float*)d_in[4];
    float* out = (float*)d_out;

    cudaFuncSetAttribute(gemm_kernel<0>,
                         cudaFuncAttributeMaxDynamicSharedMemorySize, GEMM_SMEM);
    cudaFuncSetAttribute(gemm_kernel<1>,
                         cudaFuncAttributeMaxDynamicSharedMemorySize, GEMM_SMEM);
    cudaFuncSetAttribute(attn_mma_kernel,
                         cudaFuncAttributeMaxDynamicSharedMemorySize,
                         ATTN_SMEM_BYTES);

    setup_kernel<<<TBLOCKS + (NX2 + 4 * NW2) / 256, 256>>>(x, Wq, Wk, Wv, Wo);

    dim3 gq(DMODEL / 128, NQ / 128, 3);
    gemm_kernel<0><<<gq, 256, GEMM_SMEM>>>(0);

    dim3 ga(SEQ / 64, NHEADS, BATCH);
    attn_mma_kernel<<<ga, 128, ATTN_SMEM_BYTES>>>();

    dim3 go(DMODEL / 128, NQ / 128, 1);
    gemm_kernel<1><<<go, 256, GEMM_SMEM>>>(out);
}